// round 1
// baseline (speedup 1.0000x reference)
#include <cuda_runtime.h>
#include <math.h>

// ---------------------------------------------------------------------------
// GroupAttentionLayer: B=4, H=W=64, C=256, RF=STRIDE=16 (windows tile exactly)
//   Q,K,V = leaky(BN(x @ W))                       [16384, 256] each
//   yout  = leaky(Q K^T / 16) V   per batch        [4096 x 4096] x [4096 x 256]
//   out   = softmax_spatial( s_c * yout ),  s_c = g1_c * rsqrt(var_c(yout)+eps)
//   (BN shift cancels inside the spatial softmax)
// ---------------------------------------------------------------------------

#define PROJ_ELEMS 4194304ull      // 16384*256
#define QB_STRIDE  1048576ll       // 4096*256 (per-batch stride in Q/K/V/yout)
#define PB_STRIDE  16777216ll      // 4096*4096 (per-batch stride in P)

static __device__ __align__(16) float g_Y[3ull * PROJ_ELEMS];   // Q,K,V (in-place BN)
static __device__ __align__(16) float g_P[4ull * 16777216ull];  // leaky scores
static __device__ __align__(16) float g_yout[PROJ_ELEMS];
static __device__ __align__(16) float g_ps[3 * 64 * 256];
static __device__ __align__(16) float g_pq[3 * 64 * 256];
static __device__ __align__(16) float g_ps2[64 * 256];
static __device__ __align__(16) float g_pq2[64 * 256];
static __device__ __align__(16) float g_scale[3 * 256];
static __device__ __align__(16) float g_shift[3 * 256];
static __device__ __align__(16) float g_sscale[256];

#define LEAKY(v) ((v) > 0.f ? (v) : 0.3f * (v))

// ---------------------------------------------------------------------------
// SGEMM: C[M,N] = epilogue(A[M,K] * op(B))
//   NT=false: B is [K,N] row-major.  NT=true: B is [N,K] row-major (B^T).
// Tile 128x128x16, 256 threads, 8x8 microtile per thread. Batched via grid.z.
// ---------------------------------------------------------------------------
template <bool NT, bool DOLEAKY>
__global__ __launch_bounds__(256, 2)
void gemm_kern(const float* __restrict__ A, const float* __restrict__ B,
               float* __restrict__ C, int M, int N, int K,
               long long sA, long long sB, long long sC, float scl)
{
    A += sA * (long long)blockIdx.z;
    B += sB * (long long)blockIdx.z;
    C += sC * (long long)blockIdx.z;

    __shared__ __align__(16) float As[16 * 128];   // As[k][m]
    __shared__ __align__(16) float Bs[16 * 128];   // Bs[k][n]

    const int tid = threadIdx.x;
    const int tx = tid & 15;          // n direction (8 cols each)
    const int ty = tid >> 4;          // m direction (8 rows each)
    const int m0 = blockIdx.x * 128;
    const int n0 = blockIdx.y * 128;

    float acc[8][8];
#pragma unroll
    for (int i = 0; i < 8; i++)
#pragma unroll
        for (int j = 0; j < 8; j++) acc[i][j] = 0.f;

    const int k4 = tid & 3;           // float4 index along K
    const int ra = tid >> 2;          // 0..63 row index

    for (int k0 = 0; k0 < K; k0 += 16) {
        // A tile (128x16) -> As[k][m], float4 along K then transpose-store
#pragma unroll
        for (int r = 0; r < 2; r++) {
            int m = ra + 64 * r;
            float4 v = *(const float4*)&A[(size_t)(m0 + m) * K + k0 + 4 * k4];
            As[(4 * k4 + 0) * 128 + m] = v.x;
            As[(4 * k4 + 1) * 128 + m] = v.y;
            As[(4 * k4 + 2) * 128 + m] = v.z;
            As[(4 * k4 + 3) * 128 + m] = v.w;
        }
        if (NT) {
#pragma unroll
            for (int r = 0; r < 2; r++) {
                int n = ra + 64 * r;
                float4 v = *(const float4*)&B[(size_t)(n0 + n) * K + k0 + 4 * k4];
                Bs[(4 * k4 + 0) * 128 + n] = v.x;
                Bs[(4 * k4 + 1) * 128 + n] = v.y;
                Bs[(4 * k4 + 2) * 128 + n] = v.z;
                Bs[(4 * k4 + 3) * 128 + n] = v.w;
            }
        } else {
            const int n4 = tid & 31;
            const int kr = tid >> 5;  // 0..7
#pragma unroll
            for (int r = 0; r < 2; r++) {
                int kk = kr + 8 * r;
                float4 v = *(const float4*)&B[(size_t)(k0 + kk) * N + n0 + 4 * n4];
                *(float4*)&Bs[kk * 128 + 4 * n4] = v;
            }
        }
        __syncthreads();

#pragma unroll
        for (int kk = 0; kk < 16; kk++) {
            float4 a0 = *(const float4*)&As[kk * 128 + ty * 8];
            float4 a1 = *(const float4*)&As[kk * 128 + ty * 8 + 4];
            float4 b0 = *(const float4*)&Bs[kk * 128 + tx * 8];
            float4 b1 = *(const float4*)&Bs[kk * 128 + tx * 8 + 4];
            float a[8] = {a0.x, a0.y, a0.z, a0.w, a1.x, a1.y, a1.z, a1.w};
            float b[8] = {b0.x, b0.y, b0.z, b0.w, b1.x, b1.y, b1.z, b1.w};
#pragma unroll
            for (int i = 0; i < 8; i++)
#pragma unroll
                for (int j = 0; j < 8; j++)
                    acc[i][j] = fmaf(a[i], b[j], acc[i][j]);
        }
        __syncthreads();
    }

#pragma unroll
    for (int i = 0; i < 8; i++) {
        float r[8];
#pragma unroll
        for (int j = 0; j < 8; j++) {
            float v = acc[i][j] * scl;
            if (DOLEAKY) v = LEAKY(v);
            r[j] = v;
        }
        float* cp = &C[(size_t)(m0 + ty * 8 + i) * N + n0 + tx * 8];
        *(float4*)cp       = make_float4(r[0], r[1], r[2], r[3]);
        *(float4*)(cp + 4) = make_float4(r[4], r[5], r[6], r[7]);
    }
}

// Per-channel partial sums over 256-row chunks (deterministic, no atomics).
// grid: (64, nproj), block 256 (thread = channel). Y laid out [rows,256].
__global__ void stats_partial(const float* __restrict__ Y,
                              float* __restrict__ ps, float* __restrict__ pq)
{
    int proj = blockIdx.y;
    int c = threadIdx.x;
    const float* p = Y + (size_t)proj * PROJ_ELEMS + (size_t)blockIdx.x * 65536ull + c;
    float s = 0.f, s2 = 0.f;
#pragma unroll 4
    for (int r = 0; r < 256; r++) {
        float v = p[(size_t)r * 256];
        s += v;
        s2 = fmaf(v, v, s2);
    }
    int o = (proj * 64 + blockIdx.x) * 256 + c;
    ps[o] = s;
    pq[o] = s2;
}

__global__ void finalize_qkv(const float* gq, const float* bq,
                             const float* gk, const float* bk,
                             const float* gv, const float* bv)
{
    int proj = blockIdx.x;
    int c = threadIdx.x;
    float s = 0.f, s2 = 0.f;
    for (int i = 0; i < 64; i++) {
        int o = (proj * 64 + i) * 256 + c;
        s += g_ps[o];
        s2 += g_pq[o];
    }
    float mu = s * (1.f / 16384.f);
    float var = s2 * (1.f / 16384.f) - mu * mu;
    float rs = rsqrtf(var + 1e-3f);
    const float* g = (proj == 0) ? gq : (proj == 1) ? gk : gv;
    const float* b = (proj == 0) ? bq : (proj == 1) ? bk : bv;
    float sc = g[c] * rs;
    g_scale[proj * 256 + c] = sc;
    g_shift[proj * 256 + c] = b[c] - mu * sc;
}

__global__ void finalize_soft(const float* __restrict__ g1)
{
    int c = threadIdx.x;
    float s = 0.f, s2 = 0.f;
    for (int i = 0; i < 64; i++) {
        int o = i * 256 + c;
        s += g_ps2[o];
        s2 += g_pq2[o];
    }
    float mu = s * (1.f / 16384.f);
    float var = s2 * (1.f / 16384.f) - mu * mu;
    g_sscale[c] = g1[c] * rsqrtf(var + 1e-3f);
}

// In-place BN + LeakyReLU over the 3 projections. float4-vectorized.
__global__ void bnleaky_kern()
{
    size_t i4 = (size_t)blockIdx.x * 256 + threadIdx.x;  // < 3,145,728
    int proj = (int)(i4 >> 20);                          // 2^20 float4 per proj
    int c4 = (int)(i4 & 63);
    float4 v = *(float4*)&g_Y[i4 * 4];
    int cb = proj * 256 + c4 * 4;
    float4 sc = *(float4*)&g_scale[cb];
    float4 sh = *(float4*)&g_shift[cb];
    v.x = fmaf(v.x, sc.x, sh.x); v.x = LEAKY(v.x);
    v.y = fmaf(v.y, sc.y, sh.y); v.y = LEAKY(v.y);
    v.z = fmaf(v.z, sc.z, sh.z); v.z = LEAKY(v.z);
    v.w = fmaf(v.w, sc.w, sh.w); v.w = LEAKY(v.w);
    *(float4*)&g_Y[i4 * 4] = v;
}

// Spatial softmax of s_c * yout per (batch, channel), over 4096 positions.
// grid: (32 channel-groups, 4 batches); block 256 = 32 spatial lanes x 8 ch.
__global__ void softmax_kern(const float* __restrict__ yout, float* __restrict__ out)
{
    int b = blockIdx.y;
    int c = blockIdx.x * 8 + (threadIdx.x & 7);
    int il = threadIdx.x >> 3;
    float s = g_sscale[c];
    const float* base = yout + (size_t)b * 1048576ull + c;
    float* obase = out + (size_t)b * 1048576ull + c;
    __shared__ float red[256];

    float mx = -3.4e38f;
    for (int i = il; i < 4096; i += 32)
        mx = fmaxf(mx, s * base[(size_t)i * 256]);
    red[threadIdx.x] = mx;
    __syncthreads();
    for (int st = 128; st >= 8; st >>= 1) {
        if (threadIdx.x < st)
            red[threadIdx.x] = fmaxf(red[threadIdx.x], red[threadIdx.x + st]);
        __syncthreads();
    }
    mx = red[threadIdx.x & 7];
    __syncthreads();

    float sum = 0.f;
    for (int i = il; i < 4096; i += 32) {
        float e = expf(s * base[(size_t)i * 256] - mx);
        obase[(size_t)i * 256] = e;
        sum += e;
    }
    red[threadIdx.x] = sum;
    __syncthreads();
    for (int st = 128; st >= 8; st >>= 1) {
        if (threadIdx.x < st)
            red[threadIdx.x] += red[threadIdx.x + st];
        __syncthreads();
    }
    float inv = 1.f / red[threadIdx.x & 7];

    for (int i = il; i < 4096; i += 32)
        obase[(size_t)i * 256] *= inv;
}

// ---------------------------------------------------------------------------
extern "C" void kernel_launch(void* const* d_in, const int* in_sizes, int n_in,
                              void* d_out, int out_size)
{
    (void)in_sizes; (void)n_in; (void)out_size;
    const float* x  = (const float*)d_in[0];
    const float* Wq = (const float*)d_in[1];
    const float* gq = (const float*)d_in[2];
    const float* bq = (const float*)d_in[3];
    const float* Wk = (const float*)d_in[4];
    const float* gk = (const float*)d_in[5];
    const float* bk = (const float*)d_in[6];
    const float* Wv = (const float*)d_in[7];
    const float* gv = (const float*)d_in[8];
    const float* bv = (const float*)d_in[9];
    const float* g1 = (const float*)d_in[10];
    float* out = (float*)d_out;

    float *pY, *pP, *pyout, *pps, *ppq, *pps2, *ppq2;
    cudaGetSymbolAddress((void**)&pY, g_Y);
    cudaGetSymbolAddress((void**)&pP, g_P);
    cudaGetSymbolAddress((void**)&pyout, g_yout);
    cudaGetSymbolAddress((void**)&pps, g_ps);
    cudaGetSymbolAddress((void**)&ppq, g_pq);
    cudaGetSymbolAddress((void**)&pps2, g_ps2);
    cudaGetSymbolAddress((void**)&ppq2, g_pq2);

    // 1) QKV projections (pre-BN), X[16384,256] @ W[256,256]
    gemm_kern<false, false><<<dim3(128, 2, 1), 256>>>(x, Wq, pY,
        16384, 256, 256, 0, 0, 0, 1.f);
    gemm_kern<false, false><<<dim3(128, 2, 1), 256>>>(x, Wk, pY + PROJ_ELEMS,
        16384, 256, 256, 0, 0, 0, 1.f);
    gemm_kern<false, false><<<dim3(128, 2, 1), 256>>>(x, Wv, pY + 2 * PROJ_ELEMS,
        16384, 256, 256, 0, 0, 0, 1.f);

    // 2) BN stats + apply BN+leaky in place
    stats_partial<<<dim3(64, 3), 256>>>(pY, pps, ppq);
    finalize_qkv<<<3, 256>>>(gq, bq, gk, bk, gv, bv);
    bnleaky_kern<<<12288, 256>>>();

    // 3) P = leaky(Q K^T / 16), batched over 4 batches
    gemm_kern<true, true><<<dim3(32, 32, 4), 256>>>(
        pY, pY + PROJ_ELEMS, pP,
        4096, 4096, 256, QB_STRIDE, QB_STRIDE, PB_STRIDE, 0.0625f);

    // 4) yout = P @ V
    gemm_kern<false, false><<<dim3(32, 2, 4), 256>>>(
        pP, pY + 2 * PROJ_ELEMS, pyout,
        4096, 256, 4096, PB_STRIDE, QB_STRIDE, QB_STRIDE, 1.f);

    // 5) variance of yout -> softmax temperature; spatial softmax
    stats_partial<<<dim3(64, 1), 256>>>(pyout, pps2, ppq2);
    finalize_soft<<<1, 256>>>(g1);
    softmax_kern<<<dim3(32, 4), 256>>>(pyout, out);
}

// round 3
// speedup vs baseline: 1.8413x; 1.8413x over previous
#include <cuda_runtime.h>
#include <math.h>
#include <cstdint>

// ---------------------------------------------------------------------------
// GroupAttentionLayer: B=4, H=W=64, C=256, RF=STRIDE=16 (windows tile exactly)
//   Q,K,V = leaky(BN(x @ W))                       [16384, 256] each
//   P     = leaky(Q K^T / 16)  per batch           [4096 x 4096]  (tf32 mma.sync)
//   yout  = P V                per batch           [4096 x 256]   (tf32 mma.sync)
//   out   = softmax_spatial( s_c * yout ),  s_c = g1_c * rsqrt(var_c(yout)+eps)
//   (BN shift cancels inside the spatial softmax)
// ---------------------------------------------------------------------------

#define PROJ_ELEMS 4194304ull      // 16384*256
#define QB_STRIDE  1048576ll       // 4096*256
#define PB_STRIDE  16777216ll      // 4096*4096

static __device__ __align__(16) float g_Y[3ull * PROJ_ELEMS];   // Q,K,V
static __device__ __align__(16) float g_Vt[4ull * 1048576ull];  // V^T [b][c][i]
static __device__ __align__(16) float g_P[4ull * 16777216ull];  // leaky scores
static __device__ __align__(16) float g_yout[PROJ_ELEMS];
static __device__ __align__(16) float g_ps[3 * 64 * 256];
static __device__ __align__(16) float g_pq[3 * 64 * 256];
static __device__ __align__(16) float g_ps2[64 * 256];
static __device__ __align__(16) float g_pq2[64 * 256];
static __device__ __align__(16) float g_scale[3 * 256];
static __device__ __align__(16) float g_shift[3 * 256];
static __device__ __align__(16) float g_sscale[256];

#define LEAKY(v) ((v) > 0.f ? (v) : 0.3f * (v))

__device__ __forceinline__ float tf32r(float x) {
    uint32_t u;
    asm("cvt.rna.tf32.f32 %0, %1;" : "=r"(u) : "f"(x));
    return __uint_as_float(u);
}

// mma.sync m16n8k8 tf32: D += A*B, row.col, fp32 accum. (sm_80+, works on sm_103)
__device__ __forceinline__ void mma_tf32(float* d, const uint32_t* a, const uint32_t* b)
{
    asm volatile(
        "mma.sync.aligned.m16n8k8.row.col.f32.tf32.tf32.f32 "
        "{%0,%1,%2,%3}, {%4,%5,%6,%7}, {%8,%9}, {%0,%1,%2,%3};\n"
        : "+f"(d[0]), "+f"(d[1]), "+f"(d[2]), "+f"(d[3])
        : "r"(a[0]), "r"(a[1]), "r"(a[2]), "r"(a[3]), "r"(b[0]), "r"(b[1]));
}

// ---------------------------------------------------------------------------
// Tensor-core tf32 GEMM: C[m0..+128, n0..+128] = epi(scl * A·B^T)
//   A: [M, KD] row-major.  B: [N, ldb] row-major with K contiguous (K-major).
//   D[m][n] = sum_k A[m][k] B[n][k].
// Block 128x128, K-chunk 32, 256 threads = 8 warps (2M x 4N), warp tile 64x32.
// SMEM holds tiles in fragment order:
//   As[((matom*4+kstep)*32 + lane)*4 + areg]   (8 matoms, 4 ksteps)  16KB
//   Bs[((natom*4+kstep)*32 + lane)*2 + breg]   (16 natoms)           16KB
// Fragment maps (m16n8k8): A: a0(r=l/4,c=l%4) a1(r+8) a2(c+4) a3(r+8,c+4)
//                          B: b0(k=l%4,n=l/4) b1(k+4)
// ---------------------------------------------------------------------------
template <bool LEPI>
__global__ __launch_bounds__(256, 2)
void tc_gemm(const float* __restrict__ Ag, const float* __restrict__ Bg,
             float* __restrict__ Cg, int KD, int ldb, int ldc,
             long long sA, long long sB, long long sC, float scl)
{
    __shared__ __align__(16) float As[4096];
    __shared__ __align__(16) float Bs[4096];

    Ag += sA * (long long)blockIdx.z;
    Bg += sB * (long long)blockIdx.z;
    Cg += sC * (long long)blockIdx.z;

    const int tid = threadIdx.x;
    const int wid = tid >> 5;
    const int lane = tid & 31;
    const int m0 = blockIdx.x * 128;
    const int n0 = blockIdx.y * 128;
    const int mw = (wid & 1) * 64;    // warp m offset (4 matoms)
    const int nw = (wid >> 1) * 32;   // warp n offset (4 natoms)

    float acc[4][4][4];
#pragma unroll
    for (int i = 0; i < 4; i++)
#pragma unroll
        for (int j = 0; j < 4; j++)
#pragma unroll
            for (int e = 0; e < 4; e++) acc[i][j][e] = 0.f;

    const int NIT = KD >> 5;
    for (int it = 0; it < NIT; it++) {
        const int k0 = it << 5;

        // ---- stage global tiles in registers ----
        float4 ra[4], rb[4];
#pragma unroll
        for (int i = 0; i < 4; i++) {
            int idx = i * 256 + tid;
            int r = idx >> 3, j = idx & 7;     // r: row (m or n), j: k/4
            ra[i] = *(const float4*)&Ag[(size_t)(m0 + r) * KD + k0 + 4 * j];
            rb[i] = *(const float4*)&Bg[(size_t)(n0 + r) * ldb + k0 + 4 * j];
        }

        if (it) __syncthreads();   // previous chunk's LDS done

        // ---- scatter-store into fragment layout ----
#pragma unroll
        for (int i = 0; i < 4; i++) {
            int idx = i * 256 + tid;
            int r = idx >> 3, j = idx & 7;
            int kstep = j >> 1;
            {   // A: matom = r>>4, mrow = r&15
                int matom = r >> 4, mrow = r & 15;
                int base = ((matom * 4 + kstep) * 32 + (mrow & 7) * 4) * 4
                         + (j & 1) * 2 + (mrow >> 3);
                float v[4] = {ra[i].x, ra[i].y, ra[i].z, ra[i].w};
#pragma unroll
                for (int e = 0; e < 4; e++) As[base + e * 4] = v[e];
            }
            {   // B: natom = r>>3, nrow = r&7
                int natom = r >> 3, nrow = r & 7;
                int base = ((natom * 4 + kstep) * 32 + nrow * 4) * 2 + (j & 1);
                float v[4] = {rb[i].x, rb[i].y, rb[i].z, rb[i].w};
#pragma unroll
                for (int e = 0; e < 4; e++) Bs[base + e * 2] = v[e];
            }
        }
        __syncthreads();

        // ---- 4 ksteps x (4 matoms x 4 natoms) mma ----
#pragma unroll
        for (int ks = 0; ks < 4; ks++) {
            uint32_t af[4][4], bf[4][2];
#pragma unroll
            for (int ma = 0; ma < 4; ma++)
                *(float4*)af[ma] =
                    *(const float4*)&As[(((mw >> 4) + ma) * 4 + ks) * 128 + lane * 4];
#pragma unroll
            for (int na = 0; na < 4; na++)
                *(float2*)bf[na] =
                    *(const float2*)&Bs[(((nw >> 3) + na) * 4 + ks) * 64 + lane * 2];
#pragma unroll
            for (int ma = 0; ma < 4; ma++)
#pragma unroll
                for (int na = 0; na < 4; na++)
                    mma_tf32(acc[ma][na], af[ma], bf[na]);
        }
    }

    // ---- epilogue: c0/c1 at (row, col..col+1), c2/c3 at (row+8, ...) ----
    const int rbase = m0 + mw + (lane >> 2);
    const int cbase = n0 + nw + (lane & 3) * 2;
#pragma unroll
    for (int ma = 0; ma < 4; ma++)
#pragma unroll
        for (int na = 0; na < 4; na++) {
            float* d = acc[ma][na];
            float o[4];
#pragma unroll
            for (int e = 0; e < 4; e++) {
                float v = d[e] * scl;
                if (LEPI) { v = LEAKY(v); v = tf32r(v); }
                o[e] = v;
            }
            size_t r0 = (size_t)(rbase + ma * 16) * ldc + cbase + na * 8;
            *(float2*)&Cg[r0]                      = make_float2(o[0], o[1]);
            *(float2*)&Cg[r0 + (size_t)8 * ldc]    = make_float2(o[2], o[3]);
        }
}

// ---------------------------------------------------------------------------
// fp32 SGEMM for QKV projections (M=16384, N=256, K=256)
// ---------------------------------------------------------------------------
__global__ __launch_bounds__(256, 2)
void gemm_kern(const float* __restrict__ A, const float* __restrict__ B,
               float* __restrict__ C, int M, int N, int K)
{
    __shared__ __align__(16) float As[16 * 128];
    __shared__ __align__(16) float Bs[16 * 128];

    const int tid = threadIdx.x;
    const int tx = tid & 15;
    const int ty = tid >> 4;
    const int m0 = blockIdx.x * 128;
    const int n0 = blockIdx.y * 128;

    float acc[8][8];
#pragma unroll
    for (int i = 0; i < 8; i++)
#pragma unroll
        for (int j = 0; j < 8; j++) acc[i][j] = 0.f;

    const int k4 = tid & 3;
    const int ra = tid >> 2;

    for (int k0 = 0; k0 < K; k0 += 16) {
#pragma unroll
        for (int r = 0; r < 2; r++) {
            int m = ra + 64 * r;
            float4 v = *(const float4*)&A[(size_t)(m0 + m) * K + k0 + 4 * k4];
            As[(4 * k4 + 0) * 128 + m] = v.x;
            As[(4 * k4 + 1) * 128 + m] = v.y;
            As[(4 * k4 + 2) * 128 + m] = v.z;
            As[(4 * k4 + 3) * 128 + m] = v.w;
        }
        {
            const int n4 = tid & 31;
            const int kr = tid >> 5;
#pragma unroll
            for (int r = 0; r < 2; r++) {
                int kk = kr + 8 * r;
                float4 v = *(const float4*)&B[(size_t)(k0 + kk) * N + n0 + 4 * n4];
                *(float4*)&Bs[kk * 128 + 4 * n4] = v;
            }
        }
        __syncthreads();

#pragma unroll
        for (int kk = 0; kk < 16; kk++) {
            float4 a0 = *(const float4*)&As[kk * 128 + ty * 8];
            float4 a1 = *(const float4*)&As[kk * 128 + ty * 8 + 4];
            float4 b0 = *(const float4*)&Bs[kk * 128 + tx * 8];
            float4 b1 = *(const float4*)&Bs[kk * 128 + tx * 8 + 4];
            float a[8] = {a0.x, a0.y, a0.z, a0.w, a1.x, a1.y, a1.z, a1.w};
            float b[8] = {b0.x, b0.y, b0.z, b0.w, b1.x, b1.y, b1.z, b1.w};
#pragma unroll
            for (int i = 0; i < 8; i++)
#pragma unroll
                for (int j = 0; j < 8; j++)
                    acc[i][j] = fmaf(a[i], b[j], acc[i][j]);
        }
        __syncthreads();
    }

#pragma unroll
    for (int i = 0; i < 8; i++) {
        float* cp = &C[(size_t)(m0 + ty * 8 + i) * N + n0 + tx * 8];
        *(float4*)cp       = make_float4(acc[i][0], acc[i][1], acc[i][2], acc[i][3]);
        *(float4*)(cp + 4) = make_float4(acc[i][4], acc[i][5], acc[i][6], acc[i][7]);
    }
}

// V [b*4096+i][c] -> Vt [b][c][i]   (32x32 smem tiles)
__global__ void transpose_v(const float* __restrict__ V, float* __restrict__ Vt)
{
    __shared__ float t[32][33];
    int b = blockIdx.z;
    int i0 = blockIdx.x * 32;
    int c0 = blockIdx.y * 32;
    int x = threadIdx.x, y = threadIdx.y;
#pragma unroll
    for (int r = 0; r < 4; r++)
        t[y + 8 * r][x] = V[(size_t)(b * 4096 + i0 + y + 8 * r) * 256 + c0 + x];
    __syncthreads();
#pragma unroll
    for (int r = 0; r < 4; r++)
        Vt[(size_t)b * 1048576 + (size_t)(c0 + y + 8 * r) * 4096 + i0 + x] = t[x][y + 8 * r];
}

// Per-channel partial sums over 256-row chunks (deterministic, no atomics).
__global__ void stats_partial(const float* __restrict__ Y,
                              float* __restrict__ ps, float* __restrict__ pq)
{
    int proj = blockIdx.y;
    int c = threadIdx.x;
    const float* p = Y + (size_t)proj * PROJ_ELEMS + (size_t)blockIdx.x * 65536ull + c;
    float s = 0.f, s2 = 0.f;
#pragma unroll 4
    for (int r = 0; r < 256; r++) {
        float v = p[(size_t)r * 256];
        s += v;
        s2 = fmaf(v, v, s2);
    }
    int o = (proj * 64 + blockIdx.x) * 256 + c;
    ps[o] = s;
    pq[o] = s2;
}

__global__ void finalize_qkv(const float* gq, const float* bq,
                             const float* gk, const float* bk,
                             const float* gv, const float* bv)
{
    int proj = blockIdx.x;
    int c = threadIdx.x;
    float s = 0.f, s2 = 0.f;
    for (int i = 0; i < 64; i++) {
        int o = (proj * 64 + i) * 256 + c;
        s += g_ps[o];
        s2 += g_pq[o];
    }
    float mu = s * (1.f / 16384.f);
    float var = s2 * (1.f / 16384.f) - mu * mu;
    float rs = rsqrtf(var + 1e-3f);
    const float* g = (proj == 0) ? gq : (proj == 1) ? gk : gv;
    const float* b = (proj == 0) ? bq : (proj == 1) ? bk : bv;
    float sc = g[c] * rs;
    g_scale[proj * 256 + c] = sc;
    g_shift[proj * 256 + c] = b[c] - mu * sc;
}

__global__ void finalize_soft(const float* __restrict__ g1)
{
    int c = threadIdx.x;
    float s = 0.f, s2 = 0.f;
    for (int i = 0; i < 64; i++) {
        int o = i * 256 + c;
        s += g_ps2[o];
        s2 += g_pq2[o];
    }
    float mu = s * (1.f / 16384.f);
    float var = s2 * (1.f / 16384.f) - mu * mu;
    g_sscale[c] = g1[c] * rsqrtf(var + 1e-3f);
}

// In-place BN + LeakyReLU + round-to-tf32 (MMA operand conditioning).
__global__ void bnleaky_kern()
{
    size_t i4 = (size_t)blockIdx.x * 256 + threadIdx.x;
    int proj = (int)(i4 >> 20);
    int c4 = (int)(i4 & 63);
    float4 v = *(float4*)&g_Y[i4 * 4];
    int cb = proj * 256 + c4 * 4;
    float4 sc = *(float4*)&g_scale[cb];
    float4 sh = *(float4*)&g_shift[cb];
    v.x = fmaf(v.x, sc.x, sh.x); v.x = tf32r(LEAKY(v.x));
    v.y = fmaf(v.y, sc.y, sh.y); v.y = tf32r(LEAKY(v.y));
    v.z = fmaf(v.z, sc.z, sh.z); v.z = tf32r(LEAKY(v.z));
    v.w = fmaf(v.w, sc.w, sh.w); v.w = tf32r(LEAKY(v.w));
    *(float4*)&g_Y[i4 * 4] = v;
}

// Spatial softmax of s_c * yout per (batch, channel), over 4096 positions.
__global__ void softmax_kern(const float* __restrict__ yout, float* __restrict__ out)
{
    int b = blockIdx.y;
    int c = blockIdx.x * 8 + (threadIdx.x & 7);
    int il = threadIdx.x >> 3;
    float s = g_sscale[c];
    const float* base = yout + (size_t)b * 1048576ull + c;
    float* obase = out + (size_t)b * 1048576ull + c;
    __shared__ float red[256];

    float mx = -3.4e38f;
    for (int i = il; i < 4096; i += 32)
        mx = fmaxf(mx, s * base[(size_t)i * 256]);
    red[threadIdx.x] = mx;
    __syncthreads();
    for (int st = 128; st >= 8; st >>= 1) {
        if (threadIdx.x < st)
            red[threadIdx.x] = fmaxf(red[threadIdx.x], red[threadIdx.x + st]);
        __syncthreads();
    }
    mx = red[threadIdx.x & 7];
    __syncthreads();

    float sum = 0.f;
    for (int i = il; i < 4096; i += 32) {
        float e = expf(s * base[(size_t)i * 256] - mx);
        obase[(size_t)i * 256] = e;
        sum += e;
    }
    red[threadIdx.x] = sum;
    __syncthreads();
    for (int st = 128; st >= 8; st >>= 1) {
        if (threadIdx.x < st)
            red[threadIdx.x] += red[threadIdx.x + st];
        __syncthreads();
    }
    float inv = 1.f / red[threadIdx.x & 7];

    for (int i = il; i < 4096; i += 32)
        obase[(size_t)i * 256] *= inv;
}

// ---------------------------------------------------------------------------
extern "C" void kernel_launch(void* const* d_in, const int* in_sizes, int n_in,
                              void* d_out, int out_size)
{
    (void)in_sizes; (void)n_in; (void)out_size;
    const float* x  = (const float*)d_in[0];
    const float* Wq = (const float*)d_in[1];
    const float* gq = (const float*)d_in[2];
    const float* bq = (const float*)d_in[3];
    const float* Wk = (const float*)d_in[4];
    const float* gk = (const float*)d_in[5];
    const float* bk = (const float*)d_in[6];
    const float* Wv = (const float*)d_in[7];
    const float* gv = (const float*)d_in[8];
    const float* bv = (const float*)d_in[9];
    const float* g1 = (const float*)d_in[10];
    float* out = (float*)d_out;

    float *pY, *pVt, *pP, *pyout, *pps, *ppq, *pps2, *ppq2;
    cudaGetSymbolAddress((void**)&pY, g_Y);
    cudaGetSymbolAddress((void**)&pVt, g_Vt);
    cudaGetSymbolAddress((void**)&pP, g_P);
    cudaGetSymbolAddress((void**)&pyout, g_yout);
    cudaGetSymbolAddress((void**)&pps, g_ps);
    cudaGetSymbolAddress((void**)&ppq, g_pq);
    cudaGetSymbolAddress((void**)&pps2, g_ps2);
    cudaGetSymbolAddress((void**)&ppq2, g_pq2);

    // 1) QKV projections (pre-BN), X[16384,256] @ W[256,256]
    gemm_kern<<<dim3(128, 2, 1), 256>>>(x, Wq, pY, 16384, 256, 256);
    gemm_kern<<<dim3(128, 2, 1), 256>>>(x, Wk, pY + PROJ_ELEMS, 16384, 256, 256);
    gemm_kern<<<dim3(128, 2, 1), 256>>>(x, Wv, pY + 2 * PROJ_ELEMS, 16384, 256, 256);

    // 2) BN stats + apply BN+leaky(+tf32 rounding) in place
    stats_partial<<<dim3(64, 3), 256>>>(pY, pps, ppq);
    finalize_qkv<<<3, 256>>>(gq, bq, gk, bk, gv, bv);
    bnleaky_kern<<<12288, 256>>>();

    // 3) V^T for K-major B loads in the second GEMM
    transpose_v<<<dim3(128, 8, 4), dim3(32, 8)>>>(pY + 2 * PROJ_ELEMS, pVt);

    // 4) P = leaky(Q K^T / 16)   — tf32 mma.sync, batched
    tc_gemm<true><<<dim3(32, 32, 4), 256>>>(
        pY, pY + PROJ_ELEMS, pP,
        256, 256, 4096, QB_STRIDE, QB_STRIDE, PB_STRIDE, 0.0625f);

    // 5) yout = P @ V            — tf32 mma.sync, B = Vt (K-major)
    tc_gemm<false><<<dim3(32, 2, 4), 256>>>(
        pP, pVt, pyout,
        4096, 4096, 256, PB_STRIDE, QB_STRIDE, QB_STRIDE, 1.f);

    // 6) variance of yout -> softmax temperature; spatial softmax
    stats_partial<<<dim3(64, 1), 256>>>(pyout, pps2, ppq2);
    finalize_soft<<<1, 256>>>(g1);
    softmax_kern<<<dim3(32, 4), 256>>>(pyout, out);
}

// round 4
// speedup vs baseline: 3.0799x; 1.6727x over previous
#include <cuda_runtime.h>
#include <math.h>
#include <cstdint>

// ---------------------------------------------------------------------------
// GroupAttentionLayer: B=4, H=W=64, C=256, RF=STRIDE=16 (windows tile exactly)
//   Q,K,V = leaky(BN(x @ W))                       [16384, 256] each
//   P     = leaky(Q K^T / 16)  per batch           [4096 x 4096]  (tf32 mma.sync)
//   yout  = P V                per batch           [4096 x 256]   (tf32 mma.sync)
//   out   = softmax_spatial( s_c * yout ),  s_c = g1_c * rsqrt(var_c(yout)+eps)
//   (BN shift cancels inside the spatial softmax)
// ---------------------------------------------------------------------------

#define PROJ_ELEMS 4194304ull      // 16384*256
#define QB_STRIDE  1048576ll       // 4096*256
#define PB_STRIDE  16777216ll      // 4096*4096

static __device__ __align__(16) float g_X[PROJ_ELEMS];          // tf32-rounded x
static __device__ __align__(16) float g_Wt[3ull * 65536ull];    // W^T, tf32-rounded
static __device__ __align__(16) float g_Y[3ull * PROJ_ELEMS];   // Q,K,V
static __device__ __align__(16) float g_Vt[4ull * 1048576ull];  // V^T [b][c][i]
static __device__ __align__(16) float g_P[4ull * 16777216ull];  // leaky scores
static __device__ __align__(16) float g_yout[PROJ_ELEMS];
static __device__ __align__(16) float g_ps[3 * 256 * 256];
static __device__ __align__(16) float g_pq[3 * 256 * 256];
static __device__ __align__(16) float g_ps2[256 * 256];
static __device__ __align__(16) float g_pq2[256 * 256];
static __device__ __align__(16) float g_scale[3 * 256];
static __device__ __align__(16) float g_shift[3 * 256];
static __device__ __align__(16) float g_sscale[256];

#define LEAKY(v) ((v) > 0.f ? (v) : 0.3f * (v))

__device__ __forceinline__ float tf32r(float x) {
    uint32_t u;
    asm("cvt.rna.tf32.f32 %0, %1;" : "=r"(u) : "f"(x));
    return __uint_as_float(u);
}

// mma.sync m16n8k8 tf32: D += A*B, row.col, fp32 accum.
__device__ __forceinline__ void mma_tf32(float* d, const uint32_t* a, const uint32_t* b)
{
    asm volatile(
        "mma.sync.aligned.m16n8k8.row.col.f32.tf32.tf32.f32 "
        "{%0,%1,%2,%3}, {%4,%5,%6,%7}, {%8,%9}, {%0,%1,%2,%3};\n"
        : "+f"(d[0]), "+f"(d[1]), "+f"(d[2]), "+f"(d[3])
        : "r"(a[0]), "r"(a[1]), "r"(a[2]), "r"(a[3]), "r"(b[0]), "r"(b[1]));
}

__device__ __forceinline__ void ldmatrix_x4(uint32_t* r, uint32_t addr)
{
    asm volatile("ldmatrix.sync.aligned.m8n8.x4.shared.b16 {%0,%1,%2,%3}, [%4];"
                 : "=r"(r[0]), "=r"(r[1]), "=r"(r[2]), "=r"(r[3]) : "r"(addr));
}
__device__ __forceinline__ void ldmatrix_x2(uint32_t* r, uint32_t addr)
{
    asm volatile("ldmatrix.sync.aligned.m8n8.x2.shared.b16 {%0,%1}, [%2];"
                 : "=r"(r[0]), "=r"(r[1]) : "r"(addr));
}

__device__ __forceinline__ uint32_t smem_u32(const void* p) {
    uint32_t a;
    asm("{ .reg .u64 t; cvta.to.shared.u64 t, %1; cvt.u32.u64 %0, t; }"
        : "=r"(a) : "l"(p));
    return a;
}

// ---------------------------------------------------------------------------
// Tensor-core tf32 GEMM: C[m0..+128, n0..+128] = epi(scl * A·B^T)
//   A: [M, KD] row-major.  B: [N, ldb] row-major, K contiguous (K-major).
// Block 128x128, K-chunk 32, 8 warps (2M x 4N), warp tile 64x32.
// SMEM tiles row-major, 32 floats/row, 16B-chunk XOR swizzle:
//   float4 chunk (row, k4) lives at row*32 + ((k4 ^ (row&7))*4)
// Fragments via ldmatrix (tf32-as-b16 trick).
// ---------------------------------------------------------------------------
template <bool LEPI>
__global__ __launch_bounds__(256, 2)
void tc_gemm(const float* __restrict__ Ag, const float* __restrict__ Bg,
             float* __restrict__ Cg, int KD, int ldb, int ldc,
             long long sA, long long sB, long long sC, float scl)
{
    __shared__ __align__(16) float As[4096];
    __shared__ __align__(16) float Bs[4096];
    const uint32_t sA32 = smem_u32(As);
    const uint32_t sB32 = smem_u32(Bs);

    Ag += sA * (long long)blockIdx.z;
    Bg += sB * (long long)blockIdx.z;
    Cg += sC * (long long)blockIdx.z;

    const int tid = threadIdx.x;
    const int wid = tid >> 5;
    const int lane = tid & 31;
    const int m0 = blockIdx.x * 128;
    const int n0 = blockIdx.y * 128;
    const int mw = (wid & 1) * 64;    // warp m offset (4 matoms of 16)
    const int nw = (wid >> 1) * 32;   // warp n offset (4 natoms of 8)

    float acc[4][4][4];
#pragma unroll
    for (int i = 0; i < 4; i++)
#pragma unroll
        for (int j = 0; j < 4; j++)
#pragma unroll
            for (int e = 0; e < 4; e++) acc[i][j][e] = 0.f;

    // ldmatrix per-thread row components
    const int lj = lane >> 3;          // matrix index 0..3
    const int lr = lane & 7;           // row within matrix
    const int a_row_in = lr + ((lj & 1) << 3);   // + (j&1)*8
    const int a_k4off = lj >> 1;                 // + (j>>1)
    const int b_row_in = lr;                     // (lanes 0-15 meaningful)
    const int b_k4off = lj & 1;

    const int NIT = KD >> 5;
    for (int it = 0; it < NIT; it++) {
        const int k0 = it << 5;

        // ---- stage global tiles (each thread: 4 float4 per tile) ----
        float4 ra[4], rb[4];
#pragma unroll
        for (int i = 0; i < 4; i++) {
            int idx = i * 256 + tid;
            int r = idx >> 3, k4 = idx & 7;
            ra[i] = *(const float4*)&Ag[(size_t)(m0 + r) * KD + k0 + 4 * k4];
            rb[i] = *(const float4*)&Bg[(size_t)(n0 + r) * ldb + k0 + 4 * k4];
        }

        if (it) __syncthreads();

#pragma unroll
        for (int i = 0; i < 4; i++) {
            int idx = i * 256 + tid;
            int r = idx >> 3, k4 = idx & 7;
            int off = r * 32 + ((k4 ^ (r & 7)) << 2);
            *(float4*)&As[off] = ra[i];
            *(float4*)&Bs[off] = rb[i];
        }
        __syncthreads();

        // ---- 4 ksteps x (4 matoms x 4 natoms) mma via ldmatrix ----
#pragma unroll
        for (int ks = 0; ks < 4; ks++) {
            uint32_t af[4][4], bf[4][2];
#pragma unroll
            for (int ma = 0; ma < 4; ma++) {
                int rowm = mw + ma * 16 + a_row_in;
                int k4 = ks * 2 + a_k4off;
                ldmatrix_x4(af[ma],
                    sA32 + (uint32_t)(rowm * 128 + ((k4 ^ (rowm & 7)) << 4)));
            }
#pragma unroll
            for (int na = 0; na < 4; na++) {
                int rown = nw + na * 8 + b_row_in;
                int k4 = ks * 2 + b_k4off;
                ldmatrix_x2(bf[na],
                    sB32 + (uint32_t)(rown * 128 + ((k4 ^ (rown & 7)) << 4)));
            }
#pragma unroll
            for (int ma = 0; ma < 4; ma++)
#pragma unroll
                for (int na = 0; na < 4; na++)
                    mma_tf32(acc[ma][na], af[ma], bf[na]);
        }
    }

    // ---- epilogue ----
    const int rbase = m0 + mw + (lane >> 2);
    const int cbase = n0 + nw + (lane & 3) * 2;
#pragma unroll
    for (int ma = 0; ma < 4; ma++)
#pragma unroll
        for (int na = 0; na < 4; na++) {
            float* d = acc[ma][na];
            float o[4];
#pragma unroll
            for (int e = 0; e < 4; e++) {
                float v = d[e] * scl;
                if (LEPI) { v = LEAKY(v); v = tf32r(v); }
                o[e] = v;
            }
            size_t r0 = (size_t)(rbase + ma * 16) * ldc + cbase + na * 8;
            *(float2*)&Cg[r0]                   = make_float2(o[0], o[1]);
            *(float2*)&Cg[r0 + (size_t)8 * ldc] = make_float2(o[2], o[3]);
        }
}

// tf32-round x into g_X (float4 per thread)
__global__ void round_x(const float* __restrict__ x)
{
    size_t i = (size_t)blockIdx.x * 256 + threadIdx.x;
    float4 v = ((const float4*)x)[i];
    v.x = tf32r(v.x); v.y = tf32r(v.y); v.z = tf32r(v.z); v.w = tf32r(v.w);
    ((float4*)g_X)[i] = v;
}

// transpose + tf32-round the three weight matrices: g_Wt[p][d][c] = W[c][d]
__global__ void prep_w(const float* __restrict__ Wq, const float* __restrict__ Wk,
                       const float* __restrict__ Wv)
{
    __shared__ float t[32][33];
    int p = blockIdx.z;
    const float* W = (p == 0) ? Wq : (p == 1) ? Wk : Wv;
    int c0 = blockIdx.x * 32, d0 = blockIdx.y * 32;
    int x = threadIdx.x, y = threadIdx.y;
#pragma unroll
    for (int r = 0; r < 4; r++)
        t[y + 8 * r][x] = W[(size_t)(c0 + y + 8 * r) * 256 + d0 + x];
    __syncthreads();
#pragma unroll
    for (int r = 0; r < 4; r++)
        g_Wt[(size_t)p * 65536 + (size_t)(d0 + y + 8 * r) * 256 + c0 + x] =
            tf32r(t[x][y + 8 * r]);
}

// V [b*4096+i][c] -> Vt [b][c][i]
__global__ void transpose_v(const float* __restrict__ V, float* __restrict__ Vt)
{
    __shared__ float t[32][33];
    int b = blockIdx.z;
    int i0 = blockIdx.x * 32;
    int c0 = blockIdx.y * 32;
    int x = threadIdx.x, y = threadIdx.y;
#pragma unroll
    for (int r = 0; r < 4; r++)
        t[y + 8 * r][x] = V[(size_t)(b * 4096 + i0 + y + 8 * r) * 256 + c0 + x];
    __syncthreads();
#pragma unroll
    for (int r = 0; r < 4; r++)
        Vt[(size_t)b * 1048576 + (size_t)(c0 + y + 8 * r) * 4096 + i0 + x] = t[x][y + 8 * r];
}

// Per-channel partial sums over 64-row chunks (deterministic, no atomics).
__global__ void stats_partial(const float* __restrict__ Y,
                              float* __restrict__ ps, float* __restrict__ pq)
{
    int proj = blockIdx.y;
    int c = threadIdx.x;
    const float* p = Y + (size_t)proj * PROJ_ELEMS + (size_t)blockIdx.x * 16384ull + c;
    float s = 0.f, s2 = 0.f;
#pragma unroll 8
    for (int r = 0; r < 64; r++) {
        float v = p[(size_t)r * 256];
        s += v;
        s2 = fmaf(v, v, s2);
    }
    int o = (proj * 256 + blockIdx.x) * 256 + c;
    ps[o] = s;
    pq[o] = s2;
}

__global__ void finalize_qkv(const float* gq, const float* bq,
                             const float* gk, const float* bk,
                             const float* gv, const float* bv)
{
    int proj = blockIdx.x;
    int c = threadIdx.x;
    float s = 0.f, s2 = 0.f;
    for (int i = 0; i < 256; i++) {
        int o = (proj * 256 + i) * 256 + c;
        s += g_ps[o];
        s2 += g_pq[o];
    }
    float mu = s * (1.f / 16384.f);
    float var = s2 * (1.f / 16384.f) - mu * mu;
    float rs = rsqrtf(var + 1e-3f);
    const float* g = (proj == 0) ? gq : (proj == 1) ? gk : gv;
    const float* b = (proj == 0) ? bq : (proj == 1) ? bk : bv;
    float sc = g[c] * rs;
    g_scale[proj * 256 + c] = sc;
    g_shift[proj * 256 + c] = b[c] - mu * sc;
}

__global__ void finalize_soft(const float* __restrict__ g1)
{
    int c = threadIdx.x;
    float s = 0.f, s2 = 0.f;
    for (int i = 0; i < 256; i++) {
        int o = i * 256 + c;
        s += g_ps2[o];
        s2 += g_pq2[o];
    }
    float mu = s * (1.f / 16384.f);
    float var = s2 * (1.f / 16384.f) - mu * mu;
    g_sscale[c] = g1[c] * rsqrtf(var + 1e-3f);
}

// In-place BN + LeakyReLU + round-to-tf32 (MMA operand conditioning).
__global__ void bnleaky_kern()
{
    size_t i4 = (size_t)blockIdx.x * 256 + threadIdx.x;
    int proj = (int)(i4 >> 20);
    int c4 = (int)(i4 & 63);
    float4 v = *(float4*)&g_Y[i4 * 4];
    int cb = proj * 256 + c4 * 4;
    float4 sc = *(float4*)&g_scale[cb];
    float4 sh = *(float4*)&g_shift[cb];
    v.x = fmaf(v.x, sc.x, sh.x); v.x = tf32r(LEAKY(v.x));
    v.y = fmaf(v.y, sc.y, sh.y); v.y = tf32r(LEAKY(v.y));
    v.z = fmaf(v.z, sc.z, sh.z); v.z = tf32r(LEAKY(v.z));
    v.w = fmaf(v.w, sc.w, sh.w); v.w = tf32r(LEAKY(v.w));
    *(float4*)&g_Y[i4 * 4] = v;
}

// Spatial softmax of s_c * yout per (batch, channel), over 4096 positions.
__global__ void softmax_kern(const float* __restrict__ yout, float* __restrict__ out)
{
    int b = blockIdx.y;
    int c = blockIdx.x * 8 + (threadIdx.x & 7);
    int il = threadIdx.x >> 3;
    float s = g_sscale[c];
    const float* base = yout + (size_t)b * 1048576ull + c;
    float* obase = out + (size_t)b * 1048576ull + c;
    __shared__ float red[256];

    float mx = -3.4e38f;
    for (int i = il; i < 4096; i += 32)
        mx = fmaxf(mx, s * base[(size_t)i * 256]);
    red[threadIdx.x] = mx;
    __syncthreads();
    for (int st = 128; st >= 8; st >>= 1) {
        if (threadIdx.x < st)
            red[threadIdx.x] = fmaxf(red[threadIdx.x], red[threadIdx.x + st]);
        __syncthreads();
    }
    mx = red[threadIdx.x & 7];
    __syncthreads();

    float sum = 0.f;
    for (int i = il; i < 4096; i += 32) {
        float e = expf(s * base[(size_t)i * 256] - mx);
        obase[(size_t)i * 256] = e;
        sum += e;
    }
    red[threadIdx.x] = sum;
    __syncthreads();
    for (int st = 128; st >= 8; st >>= 1) {
        if (threadIdx.x < st)
            red[threadIdx.x] += red[threadIdx.x + st];
        __syncthreads();
    }
    float inv = 1.f / red[threadIdx.x & 7];

    for (int i = il; i < 4096; i += 32)
        obase[(size_t)i * 256] *= inv;
}

// ---------------------------------------------------------------------------
extern "C" void kernel_launch(void* const* d_in, const int* in_sizes, int n_in,
                              void* d_out, int out_size)
{
    (void)in_sizes; (void)n_in; (void)out_size;
    const float* x  = (const float*)d_in[0];
    const float* Wq = (const float*)d_in[1];
    const float* gq = (const float*)d_in[2];
    const float* bq = (const float*)d_in[3];
    const float* Wk = (const float*)d_in[4];
    const float* gk = (const float*)d_in[5];
    const float* bk = (const float*)d_in[6];
    const float* Wv = (const float*)d_in[7];
    const float* gv = (const float*)d_in[8];
    const float* bv = (const float*)d_in[9];
    const float* g1 = (const float*)d_in[10];
    float* out = (float*)d_out;

    float *pX, *pWt, *pY, *pVt, *pP, *pyout, *pps, *ppq, *pps2, *ppq2;
    cudaGetSymbolAddress((void**)&pX, g_X);
    cudaGetSymbolAddress((void**)&pWt, g_Wt);
    cudaGetSymbolAddress((void**)&pY, g_Y);
    cudaGetSymbolAddress((void**)&pVt, g_Vt);
    cudaGetSymbolAddress((void**)&pP, g_P);
    cudaGetSymbolAddress((void**)&pyout, g_yout);
    cudaGetSymbolAddress((void**)&pps, g_ps);
    cudaGetSymbolAddress((void**)&ppq, g_pq);
    cudaGetSymbolAddress((void**)&pps2, g_ps2);
    cudaGetSymbolAddress((void**)&ppq2, g_pq2);

    // 0) condition operands: round x to tf32; transpose+round weights
    round_x<<<4096, 256>>>(x);
    prep_w<<<dim3(8, 8, 3), dim3(32, 8)>>>(Wq, Wk, Wv);

    // 1) QKV projections (pre-BN) on tensor cores: Y = X @ W  (B = W^T K-major)
    tc_gemm<false><<<dim3(128, 2, 1), 256>>>(pX, pWt, pY,
        256, 256, 256, 0, 0, 0, 1.f);
    tc_gemm<false><<<dim3(128, 2, 1), 256>>>(pX, pWt + 65536, pY + PROJ_ELEMS,
        256, 256, 256, 0, 0, 0, 1.f);
    tc_gemm<false><<<dim3(128, 2, 1), 256>>>(pX, pWt + 131072, pY + 2 * PROJ_ELEMS,
        256, 256, 256, 0, 0, 0, 1.f);

    // 2) BN stats + apply BN+leaky(+tf32 rounding) in place
    stats_partial<<<dim3(256, 3), 256>>>(pY, pps, ppq);
    finalize_qkv<<<3, 256>>>(gq, bq, gk, bk, gv, bv);
    bnleaky_kern<<<12288, 256>>>();

    // 3) V^T for K-major B loads in the second big GEMM
    transpose_v<<<dim3(128, 8, 4), dim3(32, 8)>>>(pY + 2 * PROJ_ELEMS, pVt);

    // 4) P = leaky(Q K^T / 16)
    tc_gemm<true><<<dim3(32, 32, 4), 256>>>(
        pY, pY + PROJ_ELEMS, pP,
        256, 256, 4096, QB_STRIDE, QB_STRIDE, PB_STRIDE, 0.0625f);

    // 5) yout = P @ V  (B = Vt K-major)
    tc_gemm<false><<<dim3(32, 2, 4), 256>>>(
        pP, pVt, pyout,
        4096, 4096, 256, PB_STRIDE, QB_STRIDE, QB_STRIDE, 1.f);

    // 6) variance of yout -> softmax temperature; spatial softmax
    stats_partial<<<dim3(256, 1), 256>>>(pyout, pps2, ppq2);
    finalize_soft<<<1, 256>>>(g1);
    softmax_kern<<<dim3(32, 4), 256>>>(pyout, out);
}

// round 5
// speedup vs baseline: 3.8111x; 1.2374x over previous
#include <cuda_runtime.h>
#include <math.h>
#include <cstdint>

// ---------------------------------------------------------------------------
// GroupAttentionLayer: B=4, H=W=64, C=256, RF=STRIDE=16 (windows tile exactly)
//   Q,K,V = leaky(BN(x @ W))                       [16384, 256] each
//   P     = leaky(Q K^T / 16)  per batch           [4096 x 4096]  (tf32 mma.sync)
//   yout  = P V                per batch           [4096 x 256]   (tf32 mma.sync)
//   out   = softmax_spatial( s_c * yout ),  s_c = g1_c * rsqrt(var_c(yout)+eps)
//   (BN shift cancels inside the spatial softmax)
// ---------------------------------------------------------------------------

#define PROJ_ELEMS 4194304ull      // 16384*256
#define QB_STRIDE  1048576ll       // 4096*256
#define PB_STRIDE  16777216ll      // 4096*4096

static __device__ __align__(16) float g_X[PROJ_ELEMS];          // tf32-rounded x
static __device__ __align__(16) float g_Wt[3ull * 65536ull];    // W^T, tf32-rounded
static __device__ __align__(16) float g_Y[3ull * PROJ_ELEMS];   // Q,K,V
static __device__ __align__(16) float g_Vt[4ull * 1048576ull];  // V^T [b][c][i]
static __device__ __align__(16) float g_P[4ull * 16777216ull];  // leaky scores
static __device__ __align__(16) float g_yout[PROJ_ELEMS];
static __device__ __align__(16) float g_ps[3 * 256 * 256];
static __device__ __align__(16) float g_pq[3 * 256 * 256];
static __device__ __align__(16) float g_ps2[256 * 256];
static __device__ __align__(16) float g_pq2[256 * 256];
static __device__ __align__(16) float g_scale[3 * 256];
static __device__ __align__(16) float g_shift[3 * 256];
static __device__ __align__(16) float g_sscale[256];

#define LEAKY(v) ((v) > 0.f ? (v) : 0.3f * (v))

__device__ __forceinline__ float tf32r(float x) {
    uint32_t u;
    asm("cvt.rna.tf32.f32 %0, %1;" : "=r"(u) : "f"(x));
    return __uint_as_float(u);
}

// mma.sync m16n8k8 tf32: D += A*B, row.col, fp32 accum.
__device__ __forceinline__ void mma_tf32(float* d, const uint32_t* a, const uint32_t* b)
{
    asm volatile(
        "mma.sync.aligned.m16n8k8.row.col.f32.tf32.tf32.f32 "
        "{%0,%1,%2,%3}, {%4,%5,%6,%7}, {%8,%9}, {%0,%1,%2,%3};\n"
        : "+f"(d[0]), "+f"(d[1]), "+f"(d[2]), "+f"(d[3])
        : "r"(a[0]), "r"(a[1]), "r"(a[2]), "r"(a[3]), "r"(b[0]), "r"(b[1]));
}

__device__ __forceinline__ void ldmatrix_x4(uint32_t* r, uint32_t addr)
{
    asm volatile("ldmatrix.sync.aligned.m8n8.x4.shared.b16 {%0,%1,%2,%3}, [%4];"
                 : "=r"(r[0]), "=r"(r[1]), "=r"(r[2]), "=r"(r[3]) : "r"(addr));
}
__device__ __forceinline__ void ldmatrix_x2(uint32_t* r, uint32_t addr)
{
    asm volatile("ldmatrix.sync.aligned.m8n8.x2.shared.b16 {%0,%1}, [%2];"
                 : "=r"(r[0]), "=r"(r[1]) : "r"(addr));
}

__device__ __forceinline__ uint32_t smem_u32(const void* p) {
    uint32_t a;
    asm("{ .reg .u64 t; cvta.to.shared.u64 t, %1; cvt.u32.u64 %0, t; }"
        : "=r"(a) : "l"(p));
    return a;
}

__device__ __forceinline__ void cp_async16(uint32_t saddr, const void* gptr)
{
    asm volatile("cp.async.cg.shared.global [%0], [%1], 16;\n"
                 :: "r"(saddr), "l"(gptr));
}
__device__ __forceinline__ void cp_commit()
{
    asm volatile("cp.async.commit_group;\n" ::: "memory");
}
template <int N>
__device__ __forceinline__ void cp_wait()
{
    asm volatile("cp.async.wait_group %0;\n" :: "n"(N) : "memory");
}

// ---------------------------------------------------------------------------
// Tensor-core tf32 GEMM: C[m0..+128, n0..+128] = epi(scl * A·B^T)
//   A: [M, KD] row-major.  B: [N, ldb] row-major, K contiguous (K-major).
// Block 128x128, K-chunk 32, 8 warps (2M x 4N), warp tile 64x32.
// Double-buffered SMEM (cp.async 2-stage), 16B-chunk XOR swizzle:
//   float4 chunk (row, k4) lives at row*32 + ((k4 ^ (row&7))*4)
// Fragments via ldmatrix (tf32-as-b16 trick).
// ---------------------------------------------------------------------------
template <bool LEPI>
__global__ __launch_bounds__(256, 2)
void tc_gemm(const float* __restrict__ Ag, const float* __restrict__ Bg,
             float* __restrict__ Cg, int KD, int ldb, int ldc,
             long long sA, long long sB, long long sC, float scl)
{
    __shared__ __align__(16) float As[2][4096];
    __shared__ __align__(16) float Bs[2][4096];
    const uint32_t sA32 = smem_u32(As);
    const uint32_t sB32 = smem_u32(Bs);

    Ag += sA * (long long)blockIdx.z;
    Bg += sB * (long long)blockIdx.z;
    Cg += sC * (long long)blockIdx.z;

    const int tid = threadIdx.x;
    const int wid = tid >> 5;
    const int lane = tid & 31;
    const int m0 = blockIdx.x * 128;
    const int n0 = blockIdx.y * 128;
    const int mw = (wid & 1) * 64;    // warp m offset (4 matoms of 16)
    const int nw = (wid >> 1) * 32;   // warp n offset (4 natoms of 8)

    float acc[4][4][4];
#pragma unroll
    for (int i = 0; i < 4; i++)
#pragma unroll
        for (int j = 0; j < 4; j++)
#pragma unroll
            for (int e = 0; e < 4; e++) acc[i][j][e] = 0.f;

    // per-thread cp.async source/dst components (4 chunks per tile)
    const int cr = tid >> 3;          // row 0..31 base (+32*i)
    const int ck4 = tid & 7;          // k4 chunk

    // ldmatrix per-thread row components
    const int lj = lane >> 3;
    const int lr = lane & 7;
    const int a_row_in = lr + ((lj & 1) << 3);
    const int a_k4off = lj >> 1;
    const int b_row_in = lr;
    const int b_k4off = lj & 1;

    const int NIT = KD >> 5;

    // ---- stage-0 prologue ----
    {
        const int k0 = 0;
#pragma unroll
        for (int i = 0; i < 4; i++) {
            int r = cr + 32 * i;
            uint32_t off = (uint32_t)((r * 32 + ((ck4 ^ (r & 7)) << 2)) * 4);
            cp_async16(sA32 + off, &Ag[(size_t)(m0 + r) * KD + k0 + 4 * ck4]);
            cp_async16(sB32 + off, &Bg[(size_t)(n0 + r) * ldb + k0 + 4 * ck4]);
        }
        cp_commit();
    }

    for (int it = 0; it < NIT; it++) {
        // ---- issue next tile into the other buffer ----
        if (it + 1 < NIT) {
            const int k0 = (it + 1) << 5;
            const uint32_t bufo = (uint32_t)(((it + 1) & 1) * 16384);
#pragma unroll
            for (int i = 0; i < 4; i++) {
                int r = cr + 32 * i;
                uint32_t off = bufo + (uint32_t)((r * 32 + ((ck4 ^ (r & 7)) << 2)) * 4);
                cp_async16(sA32 + off, &Ag[(size_t)(m0 + r) * KD + k0 + 4 * ck4]);
                cp_async16(sB32 + off, &Bg[(size_t)(n0 + r) * ldb + k0 + 4 * ck4]);
            }
            cp_commit();
            cp_wait<1>();
        } else {
            cp_wait<0>();
        }
        __syncthreads();

        // ---- compute on buffer it&1 ----
        const uint32_t bA = sA32 + (uint32_t)((it & 1) * 16384);
        const uint32_t bB = sB32 + (uint32_t)((it & 1) * 16384);
#pragma unroll
        for (int ks = 0; ks < 4; ks++) {
            uint32_t af[4][4], bf[4][2];
#pragma unroll
            for (int ma = 0; ma < 4; ma++) {
                int rowm = mw + ma * 16 + a_row_in;
                int k4 = ks * 2 + a_k4off;
                ldmatrix_x4(af[ma], bA + (uint32_t)(rowm * 128 + ((k4 ^ (rowm & 7)) << 4)));
            }
#pragma unroll
            for (int na = 0; na < 4; na++) {
                int rown = nw + na * 8 + b_row_in;
                int k4 = ks * 2 + b_k4off;
                ldmatrix_x2(bf[na], bB + (uint32_t)(rown * 128 + ((k4 ^ (rown & 7)) << 4)));
            }
#pragma unroll
            for (int ma = 0; ma < 4; ma++)
#pragma unroll
                for (int na = 0; na < 4; na++)
                    mma_tf32(acc[ma][na], af[ma], bf[na]);
        }
        __syncthreads();   // all warps done with buffer it&1 before it is refilled
    }

    // ---- epilogue ----
    const int rbase = m0 + mw + (lane >> 2);
    const int cbase = n0 + nw + (lane & 3) * 2;
#pragma unroll
    for (int ma = 0; ma < 4; ma++)
#pragma unroll
        for (int na = 0; na < 4; na++) {
            float* d = acc[ma][na];
            float o[4];
#pragma unroll
            for (int e = 0; e < 4; e++) {
                float v = d[e] * scl;
                if (LEPI) { v = LEAKY(v); v = tf32r(v); }
                o[e] = v;
            }
            size_t r0 = (size_t)(rbase + ma * 16) * ldc + cbase + na * 8;
            *(float2*)&Cg[r0]                   = make_float2(o[0], o[1]);
            *(float2*)&Cg[r0 + (size_t)8 * ldc] = make_float2(o[2], o[3]);
        }
}

// tf32-round x into g_X (float4 per thread)
__global__ void round_x(const float* __restrict__ x)
{
    size_t i = (size_t)blockIdx.x * 256 + threadIdx.x;
    float4 v = ((const float4*)x)[i];
    v.x = tf32r(v.x); v.y = tf32r(v.y); v.z = tf32r(v.z); v.w = tf32r(v.w);
    ((float4*)g_X)[i] = v;
}

// transpose + tf32-round the three weight matrices: g_Wt[p][d][c] = W[c][d]
__global__ void prep_w(const float* __restrict__ Wq, const float* __restrict__ Wk,
                       const float* __restrict__ Wv)
{
    __shared__ float t[32][33];
    int p = blockIdx.z;
    const float* W = (p == 0) ? Wq : (p == 1) ? Wk : Wv;
    int c0 = blockIdx.x * 32, d0 = blockIdx.y * 32;
    int x = threadIdx.x, y = threadIdx.y;
#pragma unroll
    for (int r = 0; r < 4; r++)
        t[y + 8 * r][x] = W[(size_t)(c0 + y + 8 * r) * 256 + d0 + x];
    __syncthreads();
#pragma unroll
    for (int r = 0; r < 4; r++)
        g_Wt[(size_t)p * 65536 + (size_t)(d0 + y + 8 * r) * 256 + c0 + x] =
            tf32r(t[x][y + 8 * r]);
}

// V [b*4096+i][c] -> Vt [b][c][i]
__global__ void transpose_v(const float* __restrict__ V, float* __restrict__ Vt)
{
    __shared__ float t[32][33];
    int b = blockIdx.z;
    int i0 = blockIdx.x * 32;
    int c0 = blockIdx.y * 32;
    int x = threadIdx.x, y = threadIdx.y;
#pragma unroll
    for (int r = 0; r < 4; r++)
        t[y + 8 * r][x] = V[(size_t)(b * 4096 + i0 + y + 8 * r) * 256 + c0 + x];
    __syncthreads();
#pragma unroll
    for (int r = 0; r < 4; r++)
        Vt[(size_t)b * 1048576 + (size_t)(c0 + y + 8 * r) * 4096 + i0 + x] = t[x][y + 8 * r];
}

// Per-channel partial sums over 64-row chunks (deterministic, no atomics).
__global__ void stats_partial(const float* __restrict__ Y,
                              float* __restrict__ ps, float* __restrict__ pq)
{
    int proj = blockIdx.y;
    int c = threadIdx.x;
    const float* p = Y + (size_t)proj * PROJ_ELEMS + (size_t)blockIdx.x * 16384ull + c;
    float s = 0.f, s2 = 0.f;
#pragma unroll 8
    for (int r = 0; r < 64; r++) {
        float v = p[(size_t)r * 256];
        s += v;
        s2 = fmaf(v, v, s2);
    }
    int o = (proj * 256 + blockIdx.x) * 256 + c;
    ps[o] = s;
    pq[o] = s2;
}

__global__ void finalize_qkv(const float* gq, const float* bq,
                             const float* gk, const float* bk,
                             const float* gv, const float* bv)
{
    int proj = blockIdx.x;
    int c = threadIdx.x;
    float s = 0.f, s2 = 0.f;
    for (int i = 0; i < 256; i++) {
        int o = (proj * 256 + i) * 256 + c;
        s += g_ps[o];
        s2 += g_pq[o];
    }
    float mu = s * (1.f / 16384.f);
    float var = s2 * (1.f / 16384.f) - mu * mu;
    float rs = rsqrtf(var + 1e-3f);
    const float* g = (proj == 0) ? gq : (proj == 1) ? gk : gv;
    const float* b = (proj == 0) ? bq : (proj == 1) ? bk : bv;
    float sc = g[c] * rs;
    g_scale[proj * 256 + c] = sc;
    g_shift[proj * 256 + c] = b[c] - mu * sc;
}

__global__ void finalize_soft(const float* __restrict__ g1)
{
    int c = threadIdx.x;
    float s = 0.f, s2 = 0.f;
    for (int i = 0; i < 256; i++) {
        int o = i * 256 + c;
        s += g_ps2[o];
        s2 += g_pq2[o];
    }
    float mu = s * (1.f / 16384.f);
    float var = s2 * (1.f / 16384.f) - mu * mu;
    g_sscale[c] = g1[c] * rsqrtf(var + 1e-3f);
}

// In-place BN + LeakyReLU + round-to-tf32 (MMA operand conditioning).
__global__ void bnleaky_kern()
{
    size_t i4 = (size_t)blockIdx.x * 256 + threadIdx.x;
    int proj = (int)(i4 >> 20);
    int c4 = (int)(i4 & 63);
    float4 v = *(float4*)&g_Y[i4 * 4];
    int cb = proj * 256 + c4 * 4;
    float4 sc = *(float4*)&g_scale[cb];
    float4 sh = *(float4*)&g_shift[cb];
    v.x = fmaf(v.x, sc.x, sh.x); v.x = tf32r(LEAKY(v.x));
    v.y = fmaf(v.y, sc.y, sh.y); v.y = tf32r(LEAKY(v.y));
    v.z = fmaf(v.z, sc.z, sh.z); v.z = tf32r(LEAKY(v.z));
    v.w = fmaf(v.w, sc.w, sh.w); v.w = tf32r(LEAKY(v.w));
    *(float4*)&g_Y[i4 * 4] = v;
}

// Spatial softmax of s_c * yout per (batch, channel), over 4096 positions.
__global__ void softmax_kern(const float* __restrict__ yout, float* __restrict__ out)
{
    int b = blockIdx.y;
    int c = blockIdx.x * 8 + (threadIdx.x & 7);
    int il = threadIdx.x >> 3;
    float s = g_sscale[c];
    const float* base = yout + (size_t)b * 1048576ull + c;
    float* obase = out + (size_t)b * 1048576ull + c;
    __shared__ float red[256];

    float mx = -3.4e38f;
    for (int i = il; i < 4096; i += 32)
        mx = fmaxf(mx, s * base[(size_t)i * 256]);
    red[threadIdx.x] = mx;
    __syncthreads();
    for (int st = 128; st >= 8; st >>= 1) {
        if (threadIdx.x < st)
            red[threadIdx.x] = fmaxf(red[threadIdx.x], red[threadIdx.x + st]);
        __syncthreads();
    }
    mx = red[threadIdx.x & 7];
    __syncthreads();

    float sum = 0.f;
    for (int i = il; i < 4096; i += 32) {
        float e = expf(s * base[(size_t)i * 256] - mx);
        obase[(size_t)i * 256] = e;
        sum += e;
    }
    red[threadIdx.x] = sum;
    __syncthreads();
    for (int st = 128; st >= 8; st >>= 1) {
        if (threadIdx.x < st)
            red[threadIdx.x] += red[threadIdx.x + st];
        __syncthreads();
    }
    float inv = 1.f / red[threadIdx.x & 7];

    for (int i = il; i < 4096; i += 32)
        obase[(size_t)i * 256] *= inv;
}

// ---------------------------------------------------------------------------
extern "C" void kernel_launch(void* const* d_in, const int* in_sizes, int n_in,
                              void* d_out, int out_size)
{
    (void)in_sizes; (void)n_in; (void)out_size;
    const float* x  = (const float*)d_in[0];
    const float* Wq = (const float*)d_in[1];
    const float* gq = (const float*)d_in[2];
    const float* bq = (const float*)d_in[3];
    const float* Wk = (const float*)d_in[4];
    const float* gk = (const float*)d_in[5];
    const float* bk = (const float*)d_in[6];
    const float* Wv = (const float*)d_in[7];
    const float* gv = (const float*)d_in[8];
    const float* bv = (const float*)d_in[9];
    const float* g1 = (const float*)d_in[10];
    float* out = (float*)d_out;

    float *pX, *pWt, *pY, *pVt, *pP, *pyout, *pps, *ppq, *pps2, *ppq2;
    cudaGetSymbolAddress((void**)&pX, g_X);
    cudaGetSymbolAddress((void**)&pWt, g_Wt);
    cudaGetSymbolAddress((void**)&pY, g_Y);
    cudaGetSymbolAddress((void**)&pVt, g_Vt);
    cudaGetSymbolAddress((void**)&pP, g_P);
    cudaGetSymbolAddress((void**)&pyout, g_yout);
    cudaGetSymbolAddress((void**)&pps, g_ps);
    cudaGetSymbolAddress((void**)&ppq, g_pq);
    cudaGetSymbolAddress((void**)&pps2, g_ps2);
    cudaGetSymbolAddress((void**)&ppq2, g_pq2);

    // 0) condition operands: round x to tf32; transpose+round weights
    round_x<<<4096, 256>>>(x);
    prep_w<<<dim3(8, 8, 3), dim3(32, 8)>>>(Wq, Wk, Wv);

    // 1) QKV projections (pre-BN) on tensor cores: Y = X @ W  (B = W^T K-major)
    tc_gemm<false><<<dim3(128, 2, 1), 256>>>(pX, pWt, pY,
        256, 256, 256, 0, 0, 0, 1.f);
    tc_gemm<false><<<dim3(128, 2, 1), 256>>>(pX, pWt + 65536, pY + PROJ_ELEMS,
        256, 256, 256, 0, 0, 0, 1.f);
    tc_gemm<false><<<dim3(128, 2, 1), 256>>>(pX, pWt + 131072, pY + 2 * PROJ_ELEMS,
        256, 256, 256, 0, 0, 0, 1.f);

    // 2) BN stats + apply BN+leaky(+tf32 rounding) in place
    stats_partial<<<dim3(256, 3), 256>>>(pY, pps, ppq);
    finalize_qkv<<<3, 256>>>(gq, bq, gk, bk, gv, bv);
    bnleaky_kern<<<12288, 256>>>();

    // 3) V^T for K-major B loads in the second big GEMM
    transpose_v<<<dim3(128, 8, 4), dim3(32, 8)>>>(pY + 2 * PROJ_ELEMS, pVt);

    // 4) P = leaky(Q K^T / 16)
    tc_gemm<true><<<dim3(32, 32, 4), 256>>>(
        pY, pY + PROJ_ELEMS, pP,
        256, 256, 4096, QB_STRIDE, QB_STRIDE, PB_STRIDE, 0.0625f);

    // 5) yout = P @ V  (B = Vt K-major)
    tc_gemm<false><<<dim3(32, 2, 4), 256>>>(
        pP, pVt, pyout,
        4096, 4096, 256, PB_STRIDE, QB_STRIDE, QB_STRIDE, 1.f);

    // 6) variance of yout -> softmax temperature; spatial softmax
    stats_partial<<<dim3(256, 1), 256>>>(pyout, pps2, ppq2);
    finalize_soft<<<1, 256>>>(g1);
    softmax_kern<<<dim3(32, 4), 256>>>(pyout, out);
}